// round 3
// baseline (speedup 1.0000x reference)
#include <cuda_runtime.h>

#define THREADS 256
#define CHUNK   512      // max K staged in smem per round (floats along K)
#define FPAD    12       // padded rank stride (10 -> 12 for 16B alignment)
#define RANK    10
#define OUTN    512

// ---------- packed f32x2 helpers ----------
__device__ __forceinline__ unsigned long long pack2(float x) {
    unsigned long long r;
    asm("mov.b64 %0, {%1, %1};" : "=l"(r) : "f"(x));
    return r;
}
__device__ __forceinline__ unsigned long long ffma2(unsigned long long a,
                                                    unsigned long long b,
                                                    unsigned long long c) {
    unsigned long long d;
    asm("fma.rn.f32x2 %0, %1, %2, %3;" : "=l"(d) : "l"(a), "l"(b), "l"(c));
    return d;
}
__device__ __forceinline__ unsigned long long fmul2(unsigned long long a,
                                                    unsigned long long b) {
    unsigned long long d;
    asm("mul.rn.f32x2 %0, %1, %2;" : "=l"(d) : "l"(a), "l"(b));
    return d;
}
__device__ __forceinline__ float2 unpack2(unsigned long long v) {
    float2 r;
    asm("mov.b64 {%0, %1}, %2;" : "=f"(r.x), "=f"(r.y) : "l"(v));
    return r;
}

// one k-step: acc[0..4] += f[k][pairs 0..4] * (x,x)   (broadcast LDS, uniform addr)
__device__ __forceinline__ void dot_k(const float* __restrict__ sfrow, float xk,
                                      unsigned long long acc[5]) {
    const ulonglong2* p = (const ulonglong2*)sfrow;       // 16B aligned (48B row)
    ulonglong2 f01 = p[0];                                // pairs (r0,r1),(r2,r3)
    ulonglong2 f23 = p[1];                                // pairs (r4,r5),(r6,r7)
    unsigned long long f4 = ((const unsigned long long*)sfrow)[4];  // (r8,r9)
    unsigned long long xx = pack2(xk);
    acc[0] = ffma2(f01.x, xx, acc[0]);
    acc[1] = ffma2(f01.y, xx, acc[1]);
    acc[2] = ffma2(f23.x, xx, acc[2]);
    acc[3] = ffma2(f23.y, xx, acc[3]);
    acc[4] = ffma2(f4,    xx, acc[4]);
}

__global__ void __launch_bounds__(THREADS)
cp_fusion_kernel(const float* __restrict__ x1, const float* __restrict__ x2,
                 const float* __restrict__ x3, const float* __restrict__ f1,
                 const float* __restrict__ f2, const float* __restrict__ f3,
                 const float* __restrict__ fo, float* __restrict__ out) {
    extern __shared__ float smem[];
    float* sf  = smem;                  // CHUNK * FPAD floats (phase buffer)
    float* sfo = smem + CHUNK * FPAD;   // OUTN * FPAD floats (f_out, staged once)

    const int tid = threadIdx.x;
    const long row = (long)blockIdx.x * THREADS + tid;

    // stage f_out once: [512][10] -> padded [512][12]
    for (int i = tid; i < OUTN * RANK; i += THREADS) {
        int o = i / RANK, r = i - o * RANK;
        sfo[o * FPAD + r] = fo[i];
    }

    const float* xs[3] = {x1, x2, x3};
    const float* fs[3] = {f1, f2, f3};
    const int    Ks[3] = {1024, 512, 768};

    unsigned long long y[5];

    #pragma unroll 1
    for (int ph = 0; ph < 3; ++ph) {
        const int K = Ks[ph];
        const float* __restrict__ xrow = xs[ph] + row * (long)K;  // hoisted row offset
        const float* __restrict__ fg   = fs[ph];
        unsigned long long acc[5] = {0ull, 0ull, 0ull, 0ull, 0ull};

        for (int kb = 0; kb < K; kb += CHUNK) {
            const int kc = min(CHUNK, K - kb);
            __syncthreads();   // previous sf contents fully consumed
            for (int i = tid; i < kc * RANK; i += THREADS) {
                int k = i / RANK, r = i - k * RANK;
                sf[k * FPAD + r] = fg[(kb + k) * RANK + r];
            }
            __syncthreads();

            const float* __restrict__ xblk = xrow + kb;
            // 16 k per unrolled body: four float4 loads batched up front (MLP~4)
            #pragma unroll 2
            for (int k0 = 0; k0 < kc; k0 += 8) {
                float4 xa = *(const float4*)(xblk + k0);
                float4 xb = *(const float4*)(xblk + k0 + 4);
                const float* fr = sf + k0 * FPAD;
                dot_k(fr + 0 * FPAD, xa.x, acc);
                dot_k(fr + 1 * FPAD, xa.y, acc);
                dot_k(fr + 2 * FPAD, xa.z, acc);
                dot_k(fr + 3 * FPAD, xa.w, acc);
                dot_k(fr + 4 * FPAD, xb.x, acc);
                dot_k(fr + 5 * FPAD, xb.y, acc);
                dot_k(fr + 6 * FPAD, xb.z, acc);
                dot_k(fr + 7 * FPAD, xb.w, acc);
            }
        }

        if (ph == 0) {
            #pragma unroll
            for (int i = 0; i < 5; ++i) y[i] = acc[i];
        } else {
            #pragma unroll
            for (int i = 0; i < 5; ++i) y[i] = fmul2(y[i], acc[i]);
        }
    }

    // epilogue: out[row][o] = sum_r y[r] * f_out[o][r], broadcast LDS of f_out
    float* __restrict__ orow = out + row * (long)OUTN;
    #pragma unroll 2
    for (int o = 0; o < OUTN; o += 4) {
        float4 res;
        float* rp = &res.x;
        #pragma unroll
        for (int j = 0; j < 4; ++j) {
            const float* fr = sfo + (o + j) * FPAD;
            const ulonglong2* p = (const ulonglong2*)fr;
            ulonglong2 f01 = p[0];
            ulonglong2 f23 = p[1];
            unsigned long long f4 = ((const unsigned long long*)fr)[4];
            unsigned long long s = fmul2(f01.x, y[0]);
            s = ffma2(f01.y, y[1], s);
            s = ffma2(f23.x, y[2], s);
            s = ffma2(f23.y, y[3], s);
            s = ffma2(f4,    y[4], s);
            float2 hv = unpack2(s);
            rp[j] = hv.x + hv.y;
        }
        *(float4*)(orow + o) = res;   // 16B aligned: row*512*4
    }
}

extern "C" void kernel_launch(void* const* d_in, const int* in_sizes, int n_in,
                              void* d_out, int out_size) {
    const float* x1 = (const float*)d_in[0];
    const float* x2 = (const float*)d_in[1];
    const float* x3 = (const float*)d_in[2];
    const float* f1 = (const float*)d_in[3];
    const float* f2 = (const float*)d_in[4];
    const float* f3 = (const float*)d_in[5];
    const float* fo = (const float*)d_in[6];
    float* out = (float*)d_out;

    const int B = in_sizes[0] / 1024;          // rows
    const int smem_bytes = (CHUNK * FPAD + OUTN * FPAD) * (int)sizeof(float); // 48 KB exactly

    dim3 grid(B / THREADS);
    cp_fusion_kernel<<<grid, THREADS, smem_bytes>>>(x1, x2, x3, f1, f2, f3, fo, out);
}

// round 17
// speedup vs baseline: 1.4838x; 1.4838x over previous
#include <cuda_runtime.h>

#define THREADS 128
#define ROWS    128      // rows per block (== THREADS)
#define KT      32       // k-chunk staged per step
#define XSTR    36       // padded floats per row in x tile (odd multiple of 4 -> conflict-free)
#define FPAD    12       // padded rank stride (10 -> 12, 48B rows, 16B aligned)
#define RANK    10
#define OUTN    512

typedef unsigned long long u64;

// ---------- packed f32x2 helpers ----------
__device__ __forceinline__ u64 pack2(float x) {
    u64 r; asm("mov.b64 %0, {%1, %1};" : "=l"(r) : "f"(x)); return r;
}
__device__ __forceinline__ u64 ffma2(u64 a, u64 b, u64 c) {
    u64 d; asm("fma.rn.f32x2 %0, %1, %2, %3;" : "=l"(d) : "l"(a), "l"(b), "l"(c)); return d;
}
__device__ __forceinline__ u64 fmul2(u64 a, u64 b) {
    u64 d; asm("mul.rn.f32x2 %0, %1, %2;" : "=l"(d) : "l"(a), "l"(b)); return d;
}
__device__ __forceinline__ float2 unpack2(u64 v) {
    float2 r; asm("mov.b64 {%0, %1}, %2;" : "=f"(r.x), "=f"(r.y) : "l"(v)); return r;
}

// acc[0..4] += f[k][pairs] * (x,x)   (factor row: broadcast LDS, 48B, 16B-aligned)
__device__ __forceinline__ void dot_k(const float* __restrict__ sfrow, float xk,
                                      u64 acc[5]) {
    const ulonglong2* p = (const ulonglong2*)sfrow;
    ulonglong2 f01 = p[0];
    ulonglong2 f23 = p[1];
    u64 f4 = ((const u64*)sfrow)[4];
    u64 xx = pack2(xk);
    acc[0] = ffma2(f01.x, xx, acc[0]);
    acc[1] = ffma2(f01.y, xx, acc[1]);
    acc[2] = ffma2(f23.x, xx, acc[2]);
    acc[3] = ffma2(f23.y, xx, acc[3]);
    acc[4] = ffma2(f4,    xx, acc[4]);
}

__global__ void __launch_bounds__(THREADS)
cp_fusion_kernel(const float* __restrict__ x1, const float* __restrict__ x2,
                 const float* __restrict__ x3, const float* __restrict__ f1,
                 const float* __restrict__ f2, const float* __restrict__ f3,
                 const float* __restrict__ fo, float* __restrict__ out) {
    extern __shared__ float smem[];
    float* xb0 = smem;                         // ROWS*XSTR floats (4608)
    float* xb1 = xb0 + ROWS * XSTR;            // ROWS*XSTR floats
    float* fb0 = xb1 + ROWS * XSTR;            // KT*FPAD floats (384)
    float* fb1 = fb0 + KT * FPAD;              // KT*FPAD floats
    // total = (2*4608 + 2*384) * 4B = 39936 B

    const int tid = threadIdx.x;
    const long rowbase = (long)blockIdx.x * ROWS;

    const float* xs[3] = {x1, x2, x3};
    const float* fs[3] = {f1, f2, f3};
    const int    Ks[3] = {1024, 512, 768};

    // per-thread staging geometry (coalesced LDG, conflict-free STS.128):
    //   thread tid loads x[srow + 16j][skol .. skol+3], j = 0..7
    const int srow = tid >> 3;          // row sub-offset (0..15)
    const int skol = (tid & 7) * 4;     // k sub-offset  (0..28)

    u64 y[5];

    #pragma unroll 1
    for (int ph = 0; ph < 3; ++ph) {
        const int K = Ks[ph];
        const float* __restrict__ xg = xs[ph] + rowbase * (long)K;
        const float* __restrict__ fg = fs[ph];
        const int nch = K / KT;
        u64 acc[5] = {0ull, 0ull, 0ull, 0ull, 0ull};

        // ---- stage chunk 0 into buffer 0 ----
        {
            const float* xgc = xg + (long)srow * K + skol;
            float* xsc = xb0 + srow * XSTR + skol;
            #pragma unroll
            for (int j = 0; j < 8; ++j)
                *(float4*)(xsc + j * 16 * XSTR) = *(const float4*)(xgc + (long)j * 16 * K);
            fb0[(tid / RANK) * FPAD + (tid % RANK)] = fg[tid];
            { int i = tid + 128; fb0[(i / RANK) * FPAD + (i % RANK)] = fg[i]; }
            if (tid < KT * RANK - 256) {
                int i = tid + 256; fb0[(i / RANK) * FPAD + (i % RANK)] = fg[i];
            }
        }
        __syncthreads();

        #pragma unroll 1
        for (int c = 0; c < nch; ++c) {
            float* xcur = (c & 1) ? xb1 : xb0;
            float* fcur = (c & 1) ? fb1 : fb0;
            float* xnxt = (c & 1) ? xb0 : xb1;
            float* fnxt = (c & 1) ? fb0 : fb1;
            const bool more = (c + 1 < nch);

            // ---- issue next-chunk global loads early (MLP ~8) ----
            float4 xr0, xr1, xr2, xr3, xr4, xr5, xr6, xr7;
            float frA = 0.f, frB = 0.f, frC = 0.f;
            if (more) {
                const float* xgc = xg + (long)srow * K + (c + 1) * KT + skol;
                xr0 = *(const float4*)(xgc + 0L  * 16 * K);
                xr1 = *(const float4*)(xgc + 1L  * 16 * K);
                xr2 = *(const float4*)(xgc + 2L  * 16 * K);
                xr3 = *(const float4*)(xgc + 3L  * 16 * K);
                xr4 = *(const float4*)(xgc + 4L  * 16 * K);
                xr5 = *(const float4*)(xgc + 5L  * 16 * K);
                xr6 = *(const float4*)(xgc + 6L  * 16 * K);
                xr7 = *(const float4*)(xgc + 7L  * 16 * K);
                const float* fgc = fg + (c + 1) * KT * RANK;
                frA = fgc[tid];
                frB = fgc[tid + 128];
                if (tid < KT * RANK - 256) frC = fgc[tid + 256];
            }

            // ---- compute 32 k from current buffers ----
            const float* xrow = xcur + tid * XSTR;
            #pragma unroll
            for (int kk = 0; kk < KT; kk += 4) {
                float4 xa = *(const float4*)(xrow + kk);
                const float* fr = fcur + kk * FPAD;
                dot_k(fr + 0 * FPAD, xa.x, acc);
                dot_k(fr + 1 * FPAD, xa.y, acc);
                dot_k(fr + 2 * FPAD, xa.z, acc);
                dot_k(fr + 3 * FPAD, xa.w, acc);
            }

            // ---- commit next chunk to the other buffer ----
            if (more) {
                float* xsc = xnxt + srow * XSTR + skol;
                *(float4*)(xsc + 0 * 16 * XSTR) = xr0;
                *(float4*)(xsc + 1 * 16 * XSTR) = xr1;
                *(float4*)(xsc + 2 * 16 * XSTR) = xr2;
                *(float4*)(xsc + 3 * 16 * XSTR) = xr3;
                *(float4*)(xsc + 4 * 16 * XSTR) = xr4;
                *(float4*)(xsc + 5 * 16 * XSTR) = xr5;
                *(float4*)(xsc + 6 * 16 * XSTR) = xr6;
                *(float4*)(xsc + 7 * 16 * XSTR) = xr7;
                fnxt[(tid / RANK) * FPAD + (tid % RANK)] = frA;
                { int i = tid + 128; fnxt[(i / RANK) * FPAD + (i % RANK)] = frB; }
                if (tid < KT * RANK - 256) {
                    int i = tid + 256; fnxt[(i / RANK) * FPAD + (i % RANK)] = frC;
                }
            }
            __syncthreads();
        }

        if (ph == 0) {
            #pragma unroll
            for (int i = 0; i < 5; ++i) y[i] = acc[i];
        } else {
            #pragma unroll
            for (int i = 0; i < 5; ++i) y[i] = fmul2(y[i], acc[i]);
        }
    }

    // ================= epilogue =================
    // stage y into smem (alias xb0): [128][FPAD]
    {
        u64* yrow = (u64*)(xb0 + tid * FPAD);
        #pragma unroll
        for (int i = 0; i < 5; ++i) yrow[i] = y[i];
    }
    __syncthreads();

    // each thread owns 4 output columns; f_out slice held in registers (40 floats)
    const int o0 = tid * 4;
    u64 fop[4][5];
    #pragma unroll
    for (int j = 0; j < 4; ++j) {
        const u64* fr = (const u64*)(fo + (o0 + j) * RANK);   // 40B offsets, 8B-aligned
        #pragma unroll
        for (int rr = 0; rr < 5; ++rr) fop[j][rr] = fr[rr];
    }

    float* __restrict__ obase = out + rowbase * OUTN + o0;
    #pragma unroll 2
    for (int row = 0; row < ROWS; ++row) {
        const float* yp = xb0 + row * FPAD;                    // broadcast LDS
        const ulonglong2* p = (const ulonglong2*)yp;
        ulonglong2 y01 = p[0];
        ulonglong2 y23 = p[1];
        u64 y4 = ((const u64*)yp)[4];
        float4 res;
        float* rp = &res.x;
        #pragma unroll
        for (int j = 0; j < 4; ++j) {
            u64 s = fmul2(fop[j][0], y01.x);
            s = ffma2(fop[j][1], y01.y, s);
            s = ffma2(fop[j][2], y23.x, s);
            s = ffma2(fop[j][3], y23.y, s);
            s = ffma2(fop[j][4], y4,    s);
            float2 hv = unpack2(s);
            rp[j] = hv.x + hv.y;
        }
        *(float4*)(obase + (long)row * OUTN) = res;            // coalesced STG.128
    }
}

extern "C" void kernel_launch(void* const* d_in, const int* in_sizes, int n_in,
                              void* d_out, int out_size) {
    const float* x1 = (const float*)d_in[0];
    const float* x2 = (const float*)d_in[1];
    const float* x3 = (const float*)d_in[2];
    const float* f1 = (const float*)d_in[3];
    const float* f2 = (const float*)d_in[4];
    const float* f3 = (const float*)d_in[5];
    const float* fo = (const float*)d_in[6];
    float* out = (float*)d_out;

    const int B = in_sizes[0] / 1024;   // 65536 rows
    const int smem_bytes = (2 * ROWS * XSTR + 2 * KT * FPAD) * (int)sizeof(float); // 39936 B

    dim3 grid(B / ROWS);                // 512 blocks
    cp_fusion_kernel<<<grid, THREADS, smem_bytes>>>(x1, x2, x3, f1, f2, f3, fo, out);
}